// round 1
// baseline (speedup 1.0000x reference)
#include <cuda_runtime.h>
#include <cstddef>

#define N_NODES 100000
#define N_EDGES 1600000
#define DIM     128
#define N_MASK  5000

// ---------------- scratch (static device globals; no allocation) ----------------
__device__ float g_deg[N_NODES];
__device__ float g_dis[N_NODES];
__device__ float g_norm[N_EDGES];
__device__ float g_h[(size_t)N_NODES * DIM];    // GEMM output (h1, then h2)
__device__ float g_agg[(size_t)N_NODES * DIM];  // aggregation buffer (agg1, then agg2)

// ---------------- degree / normalization ----------------
__global__ void deg_init_k() {
    int i = blockIdx.x * 256 + threadIdx.x;
    if (i < N_NODES) g_deg[i] = 0.f;
}

__global__ void deg_acc_k(const int* __restrict__ dst, const float* __restrict__ w) {
    int e = blockIdx.x * 256 + threadIdx.x;
    if (e < N_EDGES) atomicAdd(&g_deg[dst[e]], w[e]);
}

__global__ void dis_k() {
    int i = blockIdx.x * 256 + threadIdx.x;
    if (i < N_NODES) g_dis[i] = rsqrtf(g_deg[i] + 1.0f);  // self-loop weight 1; deg+1 > 0 always
}

__global__ void norm_k(const int* __restrict__ src, const int* __restrict__ dst,
                       const float* __restrict__ w) {
    int e = blockIdx.x * 256 + threadIdx.x;
    if (e < N_EDGES) g_norm[e] = g_dis[src[e]] * w[e] * g_dis[dst[e]];
}

// ---------------- dense GEMM: Y[n,128] = relu?(X[n,128]) @ W[128,128] ----------------
// 256 threads, 128 rows per block, full 128 cols. Thread tile 8x8.
__global__ void gemm_k(const float* __restrict__ X, const float* __restrict__ W,
                       float* __restrict__ Y, int doRelu) {
    extern __shared__ float sm[];
    float (*Ws)[132] = (float(*)[132])sm;                 // 128 x 132 (pad keeps 16B align)
    float (*Xs)[129] = (float(*)[129])(sm + 128 * 132);   // 128 x 129 (pad breaks bank conflicts)

    const int tid   = threadIdx.x;
    const int rbase = blockIdx.x * 128;

    // stage W (16384 floats, vectorized)
    for (int i = tid; i < 128 * 32; i += 256) {
        int r = i >> 5, c = i & 31;
        float4 v = ((const float4*)W)[i];
        Ws[r][c * 4 + 0] = v.x; Ws[r][c * 4 + 1] = v.y;
        Ws[r][c * 4 + 2] = v.z; Ws[r][c * 4 + 3] = v.w;
    }
    // stage X tile (with optional relu, row guard)
    for (int i = tid; i < 128 * 32; i += 256) {
        int r = i >> 5, c = i & 31;
        int row = rbase + r;
        float4 v = make_float4(0.f, 0.f, 0.f, 0.f);
        if (row < N_NODES) v = ((const float4*)(X + (size_t)row * DIM))[c];
        if (doRelu) {
            v.x = fmaxf(v.x, 0.f); v.y = fmaxf(v.y, 0.f);
            v.z = fmaxf(v.z, 0.f); v.w = fmaxf(v.w, 0.f);
        }
        Xs[r][c * 4 + 0] = v.x; Xs[r][c * 4 + 1] = v.y;
        Xs[r][c * 4 + 2] = v.z; Xs[r][c * 4 + 3] = v.w;
    }
    __syncthreads();

    const int ty = tid >> 4;   // 16 row groups of 8 rows
    const int tx = tid & 15;   // 16 col groups of 8 cols

    float acc[8][8];
#pragma unroll
    for (int i = 0; i < 8; i++)
#pragma unroll
        for (int j = 0; j < 8; j++) acc[i][j] = 0.f;

#pragma unroll 4
    for (int k = 0; k < 128; k++) {
        float a[8];
#pragma unroll
        for (int i = 0; i < 8; i++) a[i] = Xs[ty * 8 + i][k];
        float4 b0 = *(const float4*)&Ws[k][tx * 8];
        float4 b1 = *(const float4*)&Ws[k][tx * 8 + 4];
        float b[8] = {b0.x, b0.y, b0.z, b0.w, b1.x, b1.y, b1.z, b1.w};
#pragma unroll
        for (int i = 0; i < 8; i++)
#pragma unroll
            for (int j = 0; j < 8; j++) acc[i][j] = fmaf(a[i], b[j], acc[i][j]);
    }

#pragma unroll
    for (int i = 0; i < 8; i++) {
        int row = rbase + ty * 8 + i;
        if (row < N_NODES) {
            float4 o0 = make_float4(acc[i][0], acc[i][1], acc[i][2], acc[i][3]);
            float4 o1 = make_float4(acc[i][4], acc[i][5], acc[i][6], acc[i][7]);
            float4* yp = (float4*)(Y + (size_t)row * DIM + tx * 8);
            yp[0] = o0; yp[1] = o1;
        }
    }
}

// ---------------- agg init: agg[i][j] = h[i][j] * dis[i]^2 + b[j]  (self-loop + bias) ----------------
__global__ void agg_init_k(const float* __restrict__ h, const float* __restrict__ b,
                           float* __restrict__ agg) {
    int i = blockIdx.x * 256 + threadIdx.x;  // over N*32 float4s
    if (i < N_NODES * 32) {
        int row = i >> 5, c4 = i & 31;
        float d  = g_dis[row];
        float d2 = d * d;
        float4 v  = ((const float4*)h)[i];
        float4 bb = ((const float4*)b)[c4];
        float4 o = make_float4(fmaf(v.x, d2, bb.x), fmaf(v.y, d2, bb.y),
                               fmaf(v.z, d2, bb.z), fmaf(v.w, d2, bb.w));
        ((float4*)agg)[i] = o;
    }
}

// ---------------- edge scatter: agg[dst] += h[src] * norm  (warp per edge, float4 red) ----------------
__global__ void scatter_k(const float* __restrict__ h, const int* __restrict__ src,
                          const int* __restrict__ dst, float* __restrict__ agg) {
    int e = blockIdx.x * 8 + (threadIdx.x >> 5);
    if (e >= N_EDGES) return;
    int lane = threadIdx.x & 31;
    int s = src[e];
    int d = dst[e];
    float nw = g_norm[e];
    float4 v = ((const float4*)(h + (size_t)s * DIM))[lane];
    v.x *= nw; v.y *= nw; v.z *= nw; v.w *= nw;
    atomicAdd(((float4*)(agg + (size_t)d * DIM)) + lane, v);
}

// ---------------- masked gather to output ----------------
__global__ void out_k(const float* __restrict__ agg, const int* __restrict__ mask,
                      const int* __restrict__ y, float* __restrict__ out, int out_size) {
    int i = blockIdx.x * 256 + threadIdx.x;  // over N_MASK*32 float4s
    if (i < N_MASK * 32) {
        int m = i >> 5, c4 = i & 31;
        ((float4*)out)[i] = ((const float4*)(agg + (size_t)mask[m] * DIM))[c4];
    }
    if (i < N_MASK && out_size >= N_MASK * DIM + N_MASK) {
        out[N_MASK * DIM + i] = (float)y[mask[i]];
    }
}

// ---------------- launch ----------------
extern "C" void kernel_launch(void* const* d_in, const int* in_sizes, int n_in,
                              void* d_out, int out_size) {
    const float* x   = (const float*)d_in[0];
    const float* ew  = (const float*)d_in[1];
    const float* W1  = (const float*)d_in[2];
    const float* b1  = (const float*)d_in[3];
    const float* W2  = (const float*)d_in[4];
    const float* b2  = (const float*)d_in[5];
    const int*   ei  = (const int*)d_in[6];
    const int*   msk = (const int*)d_in[7];
    const int*   y   = (const int*)d_in[8];
    float*       out = (float*)d_out;

    const int* src = ei;            // edge_index[0]
    const int* dst = ei + N_EDGES;  // edge_index[1]

    float* hbuf;  cudaGetSymbolAddress((void**)&hbuf, g_h);
    float* abuf;  cudaGetSymbolAddress((void**)&abuf, g_agg);

    const int smem = (128 * 132 + 128 * 129) * (int)sizeof(float);
    cudaFuncSetAttribute(gemm_k, cudaFuncAttributeMaxDynamicSharedMemorySize, smem);

    const int NB_N  = (N_NODES + 255) / 256;
    const int NB_E  = (N_EDGES + 255) / 256;
    const int NB_G  = (N_NODES + 127) / 128;
    const int NB_A  = (N_NODES * 32 + 255) / 256;
    const int NB_S  = (N_EDGES + 7) / 8;
    const int NB_O  = (N_MASK * 32 + 255) / 256;

    // normalization precompute (shared by both layers)
    deg_init_k<<<NB_N, 256>>>();
    deg_acc_k<<<NB_E, 256>>>(dst, ew);
    dis_k<<<NB_N, 256>>>();
    norm_k<<<NB_E, 256>>>(src, dst, ew);

    // layer 1: h1 = x @ W1 ; agg1 = self-loop + bias + edge scatter
    gemm_k<<<NB_G, 256, smem>>>(x, W1, hbuf, 0);
    agg_init_k<<<NB_A, 256>>>(hbuf, b1, abuf);
    scatter_k<<<NB_S, 256>>>(hbuf, src, dst, abuf);

    // layer 2: h2 = relu(agg1) @ W2 ; agg2 = self-loop + bias + edge scatter
    gemm_k<<<NB_G, 256, smem>>>(abuf, W2, hbuf, 1);
    agg_init_k<<<NB_A, 256>>>(hbuf, b2, abuf);
    scatter_k<<<NB_S, 256>>>(hbuf, src, dst, abuf);

    // masked output (+ y as float in the tail)
    out_k<<<NB_O, 256>>>(abuf, msk, y, out, out_size);
}

// round 2
// speedup vs baseline: 1.4587x; 1.4587x over previous
#include <cuda_runtime.h>
#include <cstddef>

#define N_NODES 100000
#define N_EDGES 1600000
#define DIM     128
#define N_MASK  5000
#define SCAN_B  1024
#define SCAN_NB ((N_NODES + SCAN_B - 1) / SCAN_B)   // 98

// ---------------- scratch (static device globals; no allocation) ----------------
__device__ int   g_cnt[N_NODES];
__device__ float g_deg[N_NODES];
__device__ float g_dis[N_NODES];
__device__ int   g_off[N_NODES + 1];
__device__ int   g_cur[N_NODES];
__device__ int   g_csrc[N_EDGES];     // CSR-by-dst: source node per slot
__device__ float g_cw[N_EDGES];       // CSR-by-dst: w_e * dis[src]
__device__ int   g_bsum[SCAN_NB];
__device__ float g_h[(size_t)N_NODES * DIM];
__device__ float g_agg[(size_t)N_NODES * DIM];

// ---------------- CSR build ----------------
__global__ void zero_k() {
    int i = blockIdx.x * 256 + threadIdx.x;
    if (i < N_NODES) { g_cnt[i] = 0; g_deg[i] = 0.f; }
}

__global__ void hist_k(const int* __restrict__ dst, const float* __restrict__ w) {
    int e = blockIdx.x * 256 + threadIdx.x;
    if (e < N_EDGES) {
        int d = dst[e];
        atomicAdd(&g_cnt[d], 1);
        atomicAdd(&g_deg[d], w[e]);
    }
}

__global__ void dis_k() {
    int i = blockIdx.x * 256 + threadIdx.x;
    if (i < N_NODES) g_dis[i] = rsqrtf(g_deg[i] + 1.0f);  // +1 = self-loop weight
}

__global__ void scan1_k() {
    __shared__ int sm[SCAN_B];
    int tid = threadIdx.x;
    int i = blockIdx.x * SCAN_B + tid;
    int v = (i < N_NODES) ? g_cnt[i] : 0;
    sm[tid] = v;
    __syncthreads();
    for (int ofs = 1; ofs < SCAN_B; ofs <<= 1) {
        int t = (tid >= ofs) ? sm[tid - ofs] : 0;
        __syncthreads();
        sm[tid] += t;
        __syncthreads();
    }
    if (i < N_NODES) g_off[i] = sm[tid] - v;           // block-local exclusive
    if (tid == SCAN_B - 1) g_bsum[blockIdx.x] = sm[tid];
}

__global__ void scan2_k() {
    if (threadIdx.x == 0 && blockIdx.x == 0) {
        int run = 0;
        for (int b = 0; b < SCAN_NB; b++) { int t = g_bsum[b]; g_bsum[b] = run; run += t; }
    }
}

__global__ void scan3_k() {
    int i = blockIdx.x * 256 + threadIdx.x;
    if (i < N_NODES) {
        int o = g_off[i] + g_bsum[i / SCAN_B];
        g_off[i] = o;
        g_cur[i] = o;
    }
    if (i == 0) g_off[N_NODES] = N_EDGES;
}

__global__ void fill_k(const int* __restrict__ src, const int* __restrict__ dst,
                       const float* __restrict__ w) {
    int e = blockIdx.x * 256 + threadIdx.x;
    if (e < N_EDGES) {
        int s = src[e], d = dst[e];
        int pos = atomicAdd(&g_cur[d], 1);
        g_csrc[pos] = s;
        g_cw[pos]   = w[e] * g_dis[s];
    }
}

// ---------------- dense GEMM: Y[n,128] = relu?(X[n,128]) @ W[128,128] ----------------
__global__ void gemm_k(const float* __restrict__ X, const float* __restrict__ W,
                       float* __restrict__ Y, int doRelu) {
    extern __shared__ float sm[];
    float (*Ws)[132] = (float(*)[132])sm;
    float (*Xs)[129] = (float(*)[129])(sm + 128 * 132);

    const int tid   = threadIdx.x;
    const int rbase = blockIdx.x * 128;

    for (int i = tid; i < 128 * 32; i += 256) {
        int r = i >> 5, c = i & 31;
        float4 v = ((const float4*)W)[i];
        Ws[r][c * 4 + 0] = v.x; Ws[r][c * 4 + 1] = v.y;
        Ws[r][c * 4 + 2] = v.z; Ws[r][c * 4 + 3] = v.w;
    }
    for (int i = tid; i < 128 * 32; i += 256) {
        int r = i >> 5, c = i & 31;
        int row = rbase + r;
        float4 v = make_float4(0.f, 0.f, 0.f, 0.f);
        if (row < N_NODES) v = ((const float4*)(X + (size_t)row * DIM))[c];
        if (doRelu) {
            v.x = fmaxf(v.x, 0.f); v.y = fmaxf(v.y, 0.f);
            v.z = fmaxf(v.z, 0.f); v.w = fmaxf(v.w, 0.f);
        }
        Xs[r][c * 4 + 0] = v.x; Xs[r][c * 4 + 1] = v.y;
        Xs[r][c * 4 + 2] = v.z; Xs[r][c * 4 + 3] = v.w;
    }
    __syncthreads();

    const int ty = tid >> 4;
    const int tx = tid & 15;

    float acc[8][8];
#pragma unroll
    for (int i = 0; i < 8; i++)
#pragma unroll
        for (int j = 0; j < 8; j++) acc[i][j] = 0.f;

#pragma unroll 4
    for (int k = 0; k < 128; k++) {
        float a[8];
#pragma unroll
        for (int i = 0; i < 8; i++) a[i] = Xs[ty * 8 + i][k];
        float4 b0 = *(const float4*)&Ws[k][tx * 8];
        float4 b1 = *(const float4*)&Ws[k][tx * 8 + 4];
        float b[8] = {b0.x, b0.y, b0.z, b0.w, b1.x, b1.y, b1.z, b1.w};
#pragma unroll
        for (int i = 0; i < 8; i++)
#pragma unroll
            for (int j = 0; j < 8; j++) acc[i][j] = fmaf(a[i], b[j], acc[i][j]);
    }

#pragma unroll
    for (int i = 0; i < 8; i++) {
        int row = rbase + ty * 8 + i;
        if (row < N_NODES) {
            float4 o0 = make_float4(acc[i][0], acc[i][1], acc[i][2], acc[i][3]);
            float4 o1 = make_float4(acc[i][4], acc[i][5], acc[i][6], acc[i][7]);
            float4* yp = (float4*)(Y + (size_t)row * DIM + tx * 8);
            yp[0] = o0; yp[1] = o1;
        }
    }
}

// ---------------- CSR aggregate: warp per dst node, register accumulation ----------------
// agg[d] = dis[d] * sum_e( cw[e] * h[csrc[e]] )  +  dis[d]^2 * h[d]  +  b
__global__ void aggregate_k(const float* __restrict__ h, const float* __restrict__ b,
                            float* __restrict__ agg) {
    int node = blockIdx.x * 8 + (threadIdx.x >> 5);
    if (node >= N_NODES) return;
    int lane = threadIdx.x & 31;

    int beg = g_off[node];
    int end = g_off[node + 1];

    float4 acc = make_float4(0.f, 0.f, 0.f, 0.f);
    for (int e0 = beg; e0 < end; e0 += 32) {
        int idx = e0 + lane;
        int s = 0; float w = 0.f;
        if (idx < end) { s = g_csrc[idx]; w = g_cw[idx]; }
        int cnt = min(32, end - e0);
#pragma unroll 4
        for (int j = 0; j < cnt; j++) {
            int   sj = __shfl_sync(0xffffffffu, s, j);
            float wj = __shfl_sync(0xffffffffu, w, j);
            float4 v = ((const float4*)(h + (size_t)sj * DIM))[lane];
            acc.x = fmaf(v.x, wj, acc.x);
            acc.y = fmaf(v.y, wj, acc.y);
            acc.z = fmaf(v.z, wj, acc.z);
            acc.w = fmaf(v.w, wj, acc.w);
        }
    }

    float dd  = g_dis[node];
    float dd2 = dd * dd;
    float4 hv = ((const float4*)(h + (size_t)node * DIM))[lane];
    float4 bb = ((const float4*)b)[lane];
    float4 o;
    o.x = fmaf(acc.x, dd, fmaf(hv.x, dd2, bb.x));
    o.y = fmaf(acc.y, dd, fmaf(hv.y, dd2, bb.y));
    o.z = fmaf(acc.z, dd, fmaf(hv.z, dd2, bb.z));
    o.w = fmaf(acc.w, dd, fmaf(hv.w, dd2, bb.w));
    ((float4*)(agg + (size_t)node * DIM))[lane] = o;
}

// ---------------- masked gather to output ----------------
__global__ void out_k(const float* __restrict__ agg, const int* __restrict__ mask,
                      const int* __restrict__ y, float* __restrict__ out, int out_size) {
    int i = blockIdx.x * 256 + threadIdx.x;
    if (i < N_MASK * 32) {
        int m = i >> 5, c4 = i & 31;
        ((float4*)out)[i] = ((const float4*)(agg + (size_t)mask[m] * DIM))[c4];
    }
    if (i < N_MASK && out_size >= N_MASK * DIM + N_MASK) {
        out[N_MASK * DIM + i] = (float)y[mask[i]];
    }
}

// ---------------- launch ----------------
extern "C" void kernel_launch(void* const* d_in, const int* in_sizes, int n_in,
                              void* d_out, int out_size) {
    const float* x   = (const float*)d_in[0];
    const float* ew  = (const float*)d_in[1];
    const float* W1  = (const float*)d_in[2];
    const float* b1  = (const float*)d_in[3];
    const float* W2  = (const float*)d_in[4];
    const float* b2  = (const float*)d_in[5];
    const int*   ei  = (const int*)d_in[6];
    const int*   msk = (const int*)d_in[7];
    const int*   y   = (const int*)d_in[8];
    float*       out = (float*)d_out;

    const int* src = ei;
    const int* dst = ei + N_EDGES;

    float* hbuf;  cudaGetSymbolAddress((void**)&hbuf, g_h);
    float* abuf;  cudaGetSymbolAddress((void**)&abuf, g_agg);

    const int smem = (128 * 132 + 128 * 129) * (int)sizeof(float);
    cudaFuncSetAttribute(gemm_k, cudaFuncAttributeMaxDynamicSharedMemorySize, smem);

    const int NB_N = (N_NODES + 255) / 256;
    const int NB_E = (N_EDGES + 255) / 256;
    const int NB_G = (N_NODES + 127) / 128;
    const int NB_W = (N_NODES + 7) / 8;        // warp-per-node aggregate
    const int NB_O = (N_MASK * 32 + 255) / 256;

    // CSR-by-dst build (shared by both layers)
    zero_k<<<NB_N, 256>>>();
    hist_k<<<NB_E, 256>>>(dst, ew);
    dis_k<<<NB_N, 256>>>();
    scan1_k<<<SCAN_NB, SCAN_B>>>();
    scan2_k<<<1, 32>>>();
    scan3_k<<<NB_N, 256>>>();
    fill_k<<<NB_E, 256>>>(src, dst, ew);

    // layer 1
    gemm_k<<<NB_G, 256, smem>>>(x, W1, hbuf, 0);
    aggregate_k<<<NB_W, 256>>>(hbuf, b1, abuf);

    // layer 2
    gemm_k<<<NB_G, 256, smem>>>(abuf, W2, hbuf, 1);
    aggregate_k<<<NB_W, 256>>>(hbuf, b2, abuf);

    out_k<<<NB_O, 256>>>(abuf, msk, y, out, out_size);
}

// round 3
// speedup vs baseline: 2.2250x; 1.5254x over previous
#include <cuda_runtime.h>
#include <cstddef>

#define N_NODES 100000
#define N_EDGES 1600000
#define DIM     128
#define N_MASK  5000
#define SCAN_B  1024
#define SCAN_NB ((N_NODES + SCAN_B - 1) / SCAN_B)   // 98

// ---------------- scratch (static device globals; no allocation) ----------------
__device__ int   g_cnt[N_NODES];
__device__ float g_deg[N_NODES];
__device__ float g_dis[N_NODES];
__device__ int   g_off[N_NODES + 1];
__device__ int   g_cur[N_NODES];
__device__ int   g_csrc[N_EDGES];     // CSR-by-dst: source node per slot
__device__ float g_cw[N_EDGES];       // CSR-by-dst: w_e * dis[src]
__device__ int   g_bsum[SCAN_NB];
__device__ float g_h[(size_t)N_NODES * DIM];    // x@W1
__device__ float g_agg[(size_t)N_NODES * DIM];  // agg1
__device__ float g_z[(size_t)N_MASK * DIM];     // S_mask * relu(agg1)
__device__ float g_h2[(size_t)N_MASK * DIM];    // z @ W2

// ---------------- CSR build ----------------
__global__ void zero_k() {
    int i = blockIdx.x * 256 + threadIdx.x;
    if (i < N_NODES) { g_cnt[i] = 0; g_deg[i] = 0.f; }
}

__global__ void hist_k(const int* __restrict__ dst, const float* __restrict__ w) {
    int e = blockIdx.x * 256 + threadIdx.x;
    if (e < N_EDGES) {
        int d = dst[e];
        atomicAdd(&g_cnt[d], 1);
        atomicAdd(&g_deg[d], w[e]);
    }
}

__global__ void dis_k() {
    int i = blockIdx.x * 256 + threadIdx.x;
    if (i < N_NODES) g_dis[i] = rsqrtf(g_deg[i] + 1.0f);  // +1 = self-loop weight
}

__global__ void scan1_k() {
    __shared__ int sm[SCAN_B];
    int tid = threadIdx.x;
    int i = blockIdx.x * SCAN_B + tid;
    int v = (i < N_NODES) ? g_cnt[i] : 0;
    sm[tid] = v;
    __syncthreads();
    for (int ofs = 1; ofs < SCAN_B; ofs <<= 1) {
        int t = (tid >= ofs) ? sm[tid - ofs] : 0;
        __syncthreads();
        sm[tid] += t;
        __syncthreads();
    }
    if (i < N_NODES) g_off[i] = sm[tid] - v;           // block-local exclusive
    if (tid == SCAN_B - 1) g_bsum[blockIdx.x] = sm[tid];
}

__global__ void scan2_k() {
    if (threadIdx.x == 0 && blockIdx.x == 0) {
        int run = 0;
        for (int b = 0; b < SCAN_NB; b++) { int t = g_bsum[b]; g_bsum[b] = run; run += t; }
    }
}

__global__ void scan3_k() {
    int i = blockIdx.x * 256 + threadIdx.x;
    if (i < N_NODES) {
        int o = g_off[i] + g_bsum[i / SCAN_B];
        g_off[i] = o;
        g_cur[i] = o;
    }
    if (i == 0) g_off[N_NODES] = N_EDGES;
}

__global__ void fill_k(const int* __restrict__ src, const int* __restrict__ dst,
                       const float* __restrict__ w) {
    int e = blockIdx.x * 256 + threadIdx.x;
    if (e < N_EDGES) {
        int s = src[e], d = dst[e];
        int pos = atomicAdd(&g_cur[d], 1);
        g_csrc[pos] = s;
        g_cw[pos]   = w[e] * g_dis[s];
    }
}

// ---------------- dense GEMM: Y[r,128] = X[r,128] @ W[128,128], r < nrows ----------------
__global__ void gemm_k(const float* __restrict__ X, const float* __restrict__ W,
                       float* __restrict__ Y, int nrows) {
    extern __shared__ float sm[];
    float (*Ws)[132] = (float(*)[132])sm;
    float (*Xs)[129] = (float(*)[129])(sm + 128 * 132);

    const int tid   = threadIdx.x;
    const int rbase = blockIdx.x * 128;

    for (int i = tid; i < 128 * 32; i += 256) {
        int r = i >> 5, c = i & 31;
        float4 v = ((const float4*)W)[i];
        Ws[r][c * 4 + 0] = v.x; Ws[r][c * 4 + 1] = v.y;
        Ws[r][c * 4 + 2] = v.z; Ws[r][c * 4 + 3] = v.w;
    }
    for (int i = tid; i < 128 * 32; i += 256) {
        int r = i >> 5, c = i & 31;
        int row = rbase + r;
        float4 v = make_float4(0.f, 0.f, 0.f, 0.f);
        if (row < nrows) v = ((const float4*)(X + (size_t)row * DIM))[c];
        Xs[r][c * 4 + 0] = v.x; Xs[r][c * 4 + 1] = v.y;
        Xs[r][c * 4 + 2] = v.z; Xs[r][c * 4 + 3] = v.w;
    }
    __syncthreads();

    const int ty = tid >> 4;
    const int tx = tid & 15;

    float acc[8][8];
#pragma unroll
    for (int i = 0; i < 8; i++)
#pragma unroll
        for (int j = 0; j < 8; j++) acc[i][j] = 0.f;

#pragma unroll 4
    for (int k = 0; k < 128; k++) {
        float a[8];
#pragma unroll
        for (int i = 0; i < 8; i++) a[i] = Xs[ty * 8 + i][k];
        float4 b0 = *(const float4*)&Ws[k][tx * 8];
        float4 b1 = *(const float4*)&Ws[k][tx * 8 + 4];
        float b[8] = {b0.x, b0.y, b0.z, b0.w, b1.x, b1.y, b1.z, b1.w};
#pragma unroll
        for (int i = 0; i < 8; i++)
#pragma unroll
            for (int j = 0; j < 8; j++) acc[i][j] = fmaf(a[i], b[j], acc[i][j]);
    }

#pragma unroll
    for (int i = 0; i < 8; i++) {
        int row = rbase + ty * 8 + i;
        if (row < nrows) {
            float4 o0 = make_float4(acc[i][0], acc[i][1], acc[i][2], acc[i][3]);
            float4 o1 = make_float4(acc[i][4], acc[i][5], acc[i][6], acc[i][7]);
            float4* yp = (float4*)(Y + (size_t)row * DIM + tx * 8);
            yp[0] = o0; yp[1] = o1;
        }
    }
}

// ---------------- layer-1 CSR aggregate: warp per dst node ----------------
// agg[d] = dis[d] * sum_e( cw[e] * h[csrc[e]] )  +  dis[d]^2 * h[d]  +  b
__global__ void aggregate_k(const float* __restrict__ h, const float* __restrict__ b,
                            float* __restrict__ agg) {
    int node = blockIdx.x * 8 + (threadIdx.x >> 5);
    if (node >= N_NODES) return;
    int lane = threadIdx.x & 31;

    int beg = g_off[node];
    int end = g_off[node + 1];

    float4 acc = make_float4(0.f, 0.f, 0.f, 0.f);
    for (int e0 = beg; e0 < end; e0 += 32) {
        int idx = e0 + lane;
        int s = 0; float w = 0.f;
        if (idx < end) { s = g_csrc[idx]; w = g_cw[idx]; }
        int cnt = min(32, end - e0);
#pragma unroll 4
        for (int j = 0; j < cnt; j++) {
            int   sj = __shfl_sync(0xffffffffu, s, j);
            float wj = __shfl_sync(0xffffffffu, w, j);
            float4 v = ((const float4*)(h + (size_t)sj * DIM))[lane];
            acc.x = fmaf(v.x, wj, acc.x);
            acc.y = fmaf(v.y, wj, acc.y);
            acc.z = fmaf(v.z, wj, acc.z);
            acc.w = fmaf(v.w, wj, acc.w);
        }
    }

    float dd  = g_dis[node];
    float dd2 = dd * dd;
    float4 hv = ((const float4*)(h + (size_t)node * DIM))[lane];
    float4 bb = ((const float4*)b)[lane];
    float4 o;
    o.x = fmaf(acc.x, dd, fmaf(hv.x, dd2, bb.x));
    o.y = fmaf(acc.y, dd, fmaf(hv.y, dd2, bb.y));
    o.z = fmaf(acc.z, dd, fmaf(hv.z, dd2, bb.z));
    o.w = fmaf(acc.w, dd, fmaf(hv.w, dd2, bb.w));
    ((float4*)(agg + (size_t)node * DIM))[lane] = o;
}

// ---------------- layer-2 masked aggregate: z[m] = S_mask * relu(agg1), warp per mask row ----------------
__global__ void layer2agg_k(const float* __restrict__ agg, const int* __restrict__ mask,
                            float* __restrict__ z) {
    int m = blockIdx.x * 8 + (threadIdx.x >> 5);
    if (m >= N_MASK) return;
    int lane = threadIdx.x & 31;
    int node = mask[m];

    int beg = g_off[node];
    int end = g_off[node + 1];

    float4 acc = make_float4(0.f, 0.f, 0.f, 0.f);
    for (int e0 = beg; e0 < end; e0 += 32) {
        int idx = e0 + lane;
        int s = 0; float w = 0.f;
        if (idx < end) { s = g_csrc[idx]; w = g_cw[idx]; }
        int cnt = min(32, end - e0);
#pragma unroll 4
        for (int j = 0; j < cnt; j++) {
            int   sj = __shfl_sync(0xffffffffu, s, j);
            float wj = __shfl_sync(0xffffffffu, w, j);
            float4 v = ((const float4*)(agg + (size_t)sj * DIM))[lane];
            v.x = fmaxf(v.x, 0.f); v.y = fmaxf(v.y, 0.f);
            v.z = fmaxf(v.z, 0.f); v.w = fmaxf(v.w, 0.f);
            acc.x = fmaf(v.x, wj, acc.x);
            acc.y = fmaf(v.y, wj, acc.y);
            acc.z = fmaf(v.z, wj, acc.z);
            acc.w = fmaf(v.w, wj, acc.w);
        }
    }

    float dd  = g_dis[node];
    float dd2 = dd * dd;
    float4 hv = ((const float4*)(agg + (size_t)node * DIM))[lane];
    hv.x = fmaxf(hv.x, 0.f); hv.y = fmaxf(hv.y, 0.f);
    hv.z = fmaxf(hv.z, 0.f); hv.w = fmaxf(hv.w, 0.f);
    float4 o;
    o.x = fmaf(acc.x, dd, hv.x * dd2);
    o.y = fmaf(acc.y, dd, hv.y * dd2);
    o.z = fmaf(acc.z, dd, hv.z * dd2);
    o.w = fmaf(acc.w, dd, hv.w * dd2);
    ((float4*)(z + (size_t)m * DIM))[lane] = o;
}

// ---------------- output epilogue: out = h2 + b2 ; tail = y[mask] ----------------
__global__ void out_k(const float* __restrict__ h2, const float* __restrict__ b2,
                      const int* __restrict__ mask, const int* __restrict__ y,
                      float* __restrict__ out, int out_size) {
    int i = blockIdx.x * 256 + threadIdx.x;
    if (i < N_MASK * 32) {
        int c4 = i & 31;
        float4 v  = ((const float4*)h2)[i];
        float4 bb = ((const float4*)b2)[c4];
        v.x += bb.x; v.y += bb.y; v.z += bb.z; v.w += bb.w;
        ((float4*)out)[i] = v;
    }
    if (i < N_MASK && out_size >= N_MASK * DIM + N_MASK) {
        out[N_MASK * DIM + i] = (float)y[mask[i]];
    }
}

// ---------------- launch ----------------
extern "C" void kernel_launch(void* const* d_in, const int* in_sizes, int n_in,
                              void* d_out, int out_size) {
    const float* x   = (const float*)d_in[0];
    const float* ew  = (const float*)d_in[1];
    const float* W1  = (const float*)d_in[2];
    const float* b1  = (const float*)d_in[3];
    const float* W2  = (const float*)d_in[4];
    const float* b2  = (const float*)d_in[5];
    const int*   ei  = (const int*)d_in[6];
    const int*   msk = (const int*)d_in[7];
    const int*   y   = (const int*)d_in[8];
    float*       out = (float*)d_out;

    const int* src = ei;
    const int* dst = ei + N_EDGES;

    float* hbuf;  cudaGetSymbolAddress((void**)&hbuf, g_h);
    float* abuf;  cudaGetSymbolAddress((void**)&abuf, g_agg);
    float* zbuf;  cudaGetSymbolAddress((void**)&zbuf, g_z);
    float* h2buf; cudaGetSymbolAddress((void**)&h2buf, g_h2);

    const int smem = (128 * 132 + 128 * 129) * (int)sizeof(float);
    cudaFuncSetAttribute(gemm_k, cudaFuncAttributeMaxDynamicSharedMemorySize, smem);

    const int NB_N  = (N_NODES + 255) / 256;
    const int NB_E  = (N_EDGES + 255) / 256;
    const int NB_G1 = (N_NODES + 127) / 128;
    const int NB_G2 = (N_MASK + 127) / 128;
    const int NB_W  = (N_NODES + 7) / 8;
    const int NB_M  = (N_MASK + 7) / 8;
    const int NB_O  = (N_MASK * 32 + 255) / 256;

    // CSR-by-dst build (shared by both layers)
    zero_k<<<NB_N, 256>>>();
    hist_k<<<NB_E, 256>>>(dst, ew);
    dis_k<<<NB_N, 256>>>();
    scan1_k<<<SCAN_NB, SCAN_B>>>();
    scan2_k<<<1, 32>>>();
    scan3_k<<<NB_N, 256>>>();
    fill_k<<<NB_E, 256>>>(src, dst, ew);

    // layer 1 (full): h = x@W1 ; agg1 = S·h + b1
    gemm_k<<<NB_G1, 256, smem>>>(x, W1, hbuf, N_NODES);
    aggregate_k<<<NB_W, 256>>>(hbuf, b1, abuf);

    // layer 2 (masked): z = S_mask·relu(agg1) ; h2 = z@W2 ; out = h2 + b2
    layer2agg_k<<<NB_M, 256>>>(abuf, msk, zbuf);
    gemm_k<<<NB_G2, 256, smem>>>(zbuf, W2, h2buf, N_MASK);

    out_k<<<NB_O, 256>>>(h2buf, b2, msk, y, out, out_size);
}